// round 6
// baseline (speedup 1.0000x reference)
#include <cuda_runtime.h>
#include <cuda_fp16.h>
#include <cstdint>

#define NG 4000      // genomes
#define NS 2048      // samples
#define NM 28000     // genes
#define NK 16000     // unique seqs

// Scratch (allocation-free: __device__ globals; zero-initialized at load)
__device__ int     k_count[NK];        // hist / scatter cursors (0 at entry & exit of every launch)
__device__ int     k_offset[NK + 1];   // CSR offsets per seq
__device__ float2  slot_np[NM];        // per CSR slot: .x = genome idx (bits), .y = pos
__device__ __half2 AB16[(size_t)NG * NS];  // interleaved (a,b) fp16 pairs, 32 MB

__device__ __forceinline__ float ex2f(float x) {
    float y;
    asm("ex2.approx.ftz.f32 %0, %1;" : "=f"(y) : "f"(x));
    return y;
}

// Bit-cast helpers (these intrinsics aren't in this toolkit's headers)
__device__ __forceinline__ unsigned h2_as_u32(__half2 h) {
    union { __half2 h; unsigned u; } c; c.h = h; return c.u;
}
__device__ __forceinline__ __half2 u32_as_h2(unsigned u) {
    union { unsigned u; __half2 h; } c; c.u = u; return c.h;
}

// 32B load of 8 (a,b) half2 pairs: non-coherent, pin in L2 (evict_last; 32MB fits easily).
__device__ __forceinline__ void ldg_el8(const __half2* p, unsigned r[8]) {
    asm("ld.global.nc.L2::evict_last.v8.b32 {%0,%1,%2,%3,%4,%5,%6,%7}, [%8];"
        : "=r"(r[0]), "=r"(r[1]), "=r"(r[2]), "=r"(r[3]),
          "=r"(r[4]), "=r"(r[5]), "=r"(r[6]), "=r"(r[7]) : "l"(p));
}

// Output stores: streaming (evict-first) so the 128MB stream never displaces AB16.
__device__ __forceinline__ void stg_cs4(float* p, float a, float b, float c, float d) {
    asm volatile("st.global.cs.v4.f32 [%0], {%1,%2,%3,%4};"
                 :: "l"(p), "f"(a), "f"(b), "f"(c), "f"(d) : "memory");
}

// ---- Pass 1: convert A,B -> interleaved fp16 pairs; piggyback seq histogram ----
// grid: NG*NS/4 threads; each converts 4 samples (one float4 from A and B).
__global__ void __launch_bounds__(256)
convert_hist_kernel(const float* __restrict__ A, const float* __restrict__ B,
                    const int* __restrict__ seq_idx) {
    const int i = blockIdx.x * blockDim.x + threadIdx.x;   // 0 .. NG*NS/4-1
    const float4 a = __ldg(reinterpret_cast<const float4*>(A) + i);
    const float4 b = __ldg(reinterpret_cast<const float4*>(B) + i);
    uint4 packed;
    packed.x = h2_as_u32(__floats2half2_rn(a.x, b.x));
    packed.y = h2_as_u32(__floats2half2_rn(a.y, b.y));
    packed.z = h2_as_u32(__floats2half2_rn(a.z, b.z));
    packed.w = h2_as_u32(__floats2half2_rn(a.w, b.w));
    reinterpret_cast<uint4*>(AB16)[i] = packed;

    if (i < NM) atomicAdd(&k_count[seq_idx[i]], 1);        // histogram (k_count: 0 -> cnt)
}

// ---- Pass 2: exclusive scan over NK counters + CSR scatter (one CTA) ----
#define SCAN_T 1024
#define VPT ((NK + SCAN_T - 1) / SCAN_T)   // 16 values per thread
__global__ void __launch_bounds__(SCAN_T)
scan_scatter_kernel(const int* __restrict__ genome_idx,
                    const int* __restrict__ seq_idx,
                    const float* __restrict__ pos) {
    __shared__ int sh[SCAN_T];
    const int tid  = threadIdx.x;
    const int base = tid * VPT;
    int vals[VPT];
    int local = 0;
#pragma unroll
    for (int i = 0; i < VPT; i++) {
        int idx = base + i;
        int v = (idx < NK) ? k_count[idx] : 0;
        vals[i] = local;             // exclusive within this thread
        local += v;
    }
    sh[tid] = local;
    __syncthreads();
    for (int off = 1; off < SCAN_T; off <<= 1) {
        int t = (tid >= off) ? sh[tid - off] : 0;
        __syncthreads();
        sh[tid] += t;
        __syncthreads();
    }
    int pre = (tid > 0) ? sh[tid - 1] : 0;
#pragma unroll
    for (int i = 0; i < VPT; i++) {
        int idx = base + i;
        if (idx < NK) k_offset[idx] = pre + vals[i];
    }
    if (tid == SCAN_T - 1) k_offset[NK] = sh[SCAN_T - 1];  // == NM
    __syncthreads();   // k_offset visible CTA-wide before scatter

    // Scatter payload into CSR (k_count: cnt -> 0, restoring invariant)
    for (int g = tid; g < NM; g += SCAN_T) {
        int k = seq_idx[g];
        int old = atomicAdd(&k_count[k], -1);              // old: cnt..1
        int slot = k_offset[k] + old - 1;
        float2 payload;
        payload.x = __int_as_float(genome_idx[g]);
        payload.y = pos[g];
        slot_np[slot] = payload;
    }
}

// ---- Pass 3: seq-major fused gather, single streaming store ----
// grid: NK CTAs; 256 threads; each thread owns 8 consecutive samples (256*8 == NS).
#define MAIN_THREADS 256
__global__ void __launch_bounds__(MAIN_THREADS, 7)
main_kernel(const float* __restrict__ bias, float* __restrict__ out) {
    const int k  = blockIdx.x;                  // output seq row
    const int s0 = threadIdx.x * 8;

    const int beg = k_offset[k];
    const int end = k_offset[k + 1];

    float acc[8];
#pragma unroll
    for (int j = 0; j < 8; j++) acc[j] = 0.f;

    int i = beg;
    // 2-gene unrolled body: two independent slot->AB16 load chains in flight
    for (; i + 2 <= end; i += 2) {
        const float2 p0 = slot_np[i];
        const float2 p1 = slot_np[i + 1];
        const int n0 = __float_as_int(p0.x);
        const int n1 = __float_as_int(p1.x);
        unsigned r0[8], r1[8];
        ldg_el8(AB16 + (size_t)n0 * NS + s0, r0);
        ldg_el8(AB16 + (size_t)n1 * NS + s0, r1);
#pragma unroll
        for (int j = 0; j < 8; j++) {
            const float2 ab = __half22float2(u32_as_h2(r0[j]));
            acc[j] = fmaf(ab.x, ex2f(-p0.y * ab.y), acc[j]);
        }
#pragma unroll
        for (int j = 0; j < 8; j++) {
            const float2 ab = __half22float2(u32_as_h2(r1[j]));
            acc[j] = fmaf(ab.x, ex2f(-p1.y * ab.y), acc[j]);
        }
    }
    if (i < end) {
        const float2 p0 = slot_np[i];
        const int n0 = __float_as_int(p0.x);
        unsigned r0[8];
        ldg_el8(AB16 + (size_t)n0 * NS + s0, r0);
#pragma unroll
        for (int j = 0; j < 8; j++) {
            const float2 ab = __half22float2(u32_as_h2(r0[j]));
            acc[j] = fmaf(ab.x, ex2f(-p0.y * ab.y), acc[j]);
        }
    }

    // G = A * 2^(1 - p*B) = 2 * A * 2^(-p*B): fold the 2 into bias.
    const float w = 2.0f * bias[k];
    float* po = out + (size_t)k * NS + s0;
    stg_cs4(po,     w * acc[0], w * acc[1], w * acc[2], w * acc[3]);
    stg_cs4(po + 4, w * acc[4], w * acc[5], w * acc[6], w * acc[7]);
}

// ---------------- launch ----------------
extern "C" void kernel_launch(void* const* d_in, const int* in_sizes, int n_in,
                              void* d_out, int out_size) {
    const float* A          = (const float*)d_in[0];   // (4000, 2048)
    const float* B          = (const float*)d_in[1];   // (4000, 2048)
    const float* bias       = (const float*)d_in[2];   // (16000,)
    const float* pos        = (const float*)d_in[3];   // (28000,)
    const int*   genome_idx = (const int*)d_in[4];     // (28000,)
    const int*   seq_idx    = (const int*)d_in[5];     // (28000,)
    float*       out        = (float*)d_out;           // (16000, 2048)

    const int n4 = (NG * NS) / 4;                      // 2,048,000 threads
    convert_hist_kernel<<<n4 / 256, 256>>>(A, B, seq_idx);
    scan_scatter_kernel<<<1, SCAN_T>>>(genome_idx, seq_idx, pos);
    main_kernel<<<NK, MAIN_THREADS>>>(bias, out);
}

// round 7
// speedup vs baseline: 1.0366x; 1.0366x over previous
#include <cuda_runtime.h>
#include <cuda_fp16.h>
#include <cstdint>

#define NG 4000      // genomes
#define NS 2048      // samples
#define NM 28000     // genes
#define NK 16000     // unique seqs

// Scratch (allocation-free: __device__ globals; zero-initialized at load)
__device__ int     k_count[NK];        // hist / scatter cursors (0 at entry & exit of every launch)
__device__ int     k_offset[NK + 1];   // CSR offsets per seq
__device__ float2  slot_np[NM];        // per CSR slot: .x = genome idx (bits), .y = pos
__device__ __half2 AB16[(size_t)NG * NS];  // interleaved (a,b) fp16 pairs, 32 MB

__device__ __forceinline__ float ex2f(float x) {
    float y;
    asm("ex2.approx.ftz.f32 %0, %1;" : "=f"(y) : "f"(x));
    return y;
}

// Bit-cast helpers (these intrinsics aren't in this toolkit's headers)
__device__ __forceinline__ unsigned h2_as_u32(__half2 h) {
    union { __half2 h; unsigned u; } c; c.h = h; return c.u;
}
__device__ __forceinline__ __half2 u32_as_h2(unsigned u) {
    union { unsigned u; __half2 h; } c; c.u = u; return c.h;
}

// 32B load of 8 (a,b) half2 pairs: non-coherent, pin in L2 (evict_last; 32MB fits easily).
__device__ __forceinline__ void ldg_el8(const __half2* p, unsigned r[8]) {
    asm("ld.global.nc.L2::evict_last.v8.b32 {%0,%1,%2,%3,%4,%5,%6,%7}, [%8];"
        : "=r"(r[0]), "=r"(r[1]), "=r"(r[2]), "=r"(r[3]),
          "=r"(r[4]), "=r"(r[5]), "=r"(r[6]), "=r"(r[7]) : "l"(p));
}

// Output stores: streaming (evict-first) so the 128MB stream never displaces AB16.
__device__ __forceinline__ void stg_cs4(float* p, float a, float b, float c, float d) {
    asm volatile("st.global.cs.v4.f32 [%0], {%1,%2,%3,%4};"
                 :: "l"(p), "f"(a), "f"(b), "f"(c), "f"(d) : "memory");
}

// ---- Pass 1: convert A,B -> interleaved fp16 pairs; piggyback seq histogram ----
// grid: NG*NS/4 threads; each converts 4 samples (one float4 from A and B).
__global__ void __launch_bounds__(256)
convert_hist_kernel(const float* __restrict__ A, const float* __restrict__ B,
                    const int* __restrict__ seq_idx) {
    const int i = blockIdx.x * blockDim.x + threadIdx.x;   // 0 .. NG*NS/4-1
    const float4 a = __ldg(reinterpret_cast<const float4*>(A) + i);
    const float4 b = __ldg(reinterpret_cast<const float4*>(B) + i);
    uint4 packed;
    packed.x = h2_as_u32(__floats2half2_rn(a.x, b.x));
    packed.y = h2_as_u32(__floats2half2_rn(a.y, b.y));
    packed.z = h2_as_u32(__floats2half2_rn(a.z, b.z));
    packed.w = h2_as_u32(__floats2half2_rn(a.w, b.w));
    reinterpret_cast<uint4*>(AB16)[i] = packed;

    if (i < NM) atomicAdd(&k_count[seq_idx[i]], 1);        // histogram (k_count: 0 -> cnt)
}

// ---- Pass 2: exclusive scan over NK counters + CSR scatter (one CTA) ----
#define SCAN_T 1024
#define VPT ((NK + SCAN_T - 1) / SCAN_T)   // 16 values per thread
__global__ void __launch_bounds__(SCAN_T)
scan_scatter_kernel(const int* __restrict__ genome_idx,
                    const int* __restrict__ seq_idx,
                    const float* __restrict__ pos) {
    __shared__ int sh[SCAN_T];
    const int tid  = threadIdx.x;
    const int base = tid * VPT;
    int vals[VPT];
    int local = 0;
#pragma unroll
    for (int i = 0; i < VPT; i++) {
        int idx = base + i;
        int v = (idx < NK) ? k_count[idx] : 0;
        vals[i] = local;             // exclusive within this thread
        local += v;
    }
    sh[tid] = local;
    __syncthreads();
    for (int off = 1; off < SCAN_T; off <<= 1) {
        int t = (tid >= off) ? sh[tid - off] : 0;
        __syncthreads();
        sh[tid] += t;
        __syncthreads();
    }
    int pre = (tid > 0) ? sh[tid - 1] : 0;
#pragma unroll
    for (int i = 0; i < VPT; i++) {
        int idx = base + i;
        if (idx < NK) k_offset[idx] = pre + vals[i];
    }
    if (tid == SCAN_T - 1) k_offset[NK] = sh[SCAN_T - 1];  // == NM
    __syncthreads();   // k_offset visible CTA-wide before scatter

    // Scatter payload into CSR (k_count: cnt -> 0, restoring invariant)
    for (int g = tid; g < NM; g += SCAN_T) {
        int k = seq_idx[g];
        int old = atomicAdd(&k_count[k], -1);              // old: cnt..1
        int slot = k_offset[k] + old - 1;
        float2 payload;
        payload.x = __int_as_float(genome_idx[g]);
        payload.y = pos[g];
        slot_np[slot] = payload;
    }
}

// ---- Pass 3: seq-major fused gather, single streaming store ----
// grid: NK CTAs; 256 threads; each thread owns 8 consecutive samples (256*8 == NS).
// NOTE: no min-blocks clamp — R6's (256,7) forced regs<=36 and spilled the hot loop.
#define MAIN_THREADS 256
__global__ void __launch_bounds__(MAIN_THREADS)
main_kernel(const float* __restrict__ bias, float* __restrict__ out) {
    const int k  = blockIdx.x;                  // output seq row
    const int s0 = threadIdx.x * 8;

    const int beg = k_offset[k];
    const int end = k_offset[k + 1];

    float acc[8];
#pragma unroll
    for (int j = 0; j < 8; j++) acc[j] = 0.f;

    int i = beg;
    // 2-gene unrolled body: two independent slot->AB16 load chains in flight
    for (; i + 2 <= end; i += 2) {
        const float2 p0 = slot_np[i];
        const float2 p1 = slot_np[i + 1];
        const int n0 = __float_as_int(p0.x);
        const int n1 = __float_as_int(p1.x);
        unsigned r0[8], r1[8];
        ldg_el8(AB16 + (size_t)n0 * NS + s0, r0);
        ldg_el8(AB16 + (size_t)n1 * NS + s0, r1);
#pragma unroll
        for (int j = 0; j < 8; j++) {
            const float2 ab = __half22float2(u32_as_h2(r0[j]));
            acc[j] = fmaf(ab.x, ex2f(-p0.y * ab.y), acc[j]);
        }
#pragma unroll
        for (int j = 0; j < 8; j++) {
            const float2 ab = __half22float2(u32_as_h2(r1[j]));
            acc[j] = fmaf(ab.x, ex2f(-p1.y * ab.y), acc[j]);
        }
    }
    if (i < end) {
        const float2 p0 = slot_np[i];
        const int n0 = __float_as_int(p0.x);
        unsigned r0[8];
        ldg_el8(AB16 + (size_t)n0 * NS + s0, r0);
#pragma unroll
        for (int j = 0; j < 8; j++) {
            const float2 ab = __half22float2(u32_as_h2(r0[j]));
            acc[j] = fmaf(ab.x, ex2f(-p0.y * ab.y), acc[j]);
        }
    }

    // G = A * 2^(1 - p*B) = 2 * A * 2^(-p*B): fold the 2 into bias.
    const float w = 2.0f * bias[k];
    float* po = out + (size_t)k * NS + s0;
    stg_cs4(po,     w * acc[0], w * acc[1], w * acc[2], w * acc[3]);
    stg_cs4(po + 4, w * acc[4], w * acc[5], w * acc[6], w * acc[7]);
}

// ---------------- launch ----------------
extern "C" void kernel_launch(void* const* d_in, const int* in_sizes, int n_in,
                              void* d_out, int out_size) {
    const float* A          = (const float*)d_in[0];   // (4000, 2048)
    const float* B          = (const float*)d_in[1];   // (4000, 2048)
    const float* bias       = (const float*)d_in[2];   // (16000,)
    const float* pos        = (const float*)d_in[3];   // (28000,)
    const int*   genome_idx = (const int*)d_in[4];     // (28000,)
    const int*   seq_idx    = (const int*)d_in[5];     // (28000,)
    float*       out        = (float*)d_out;           // (16000, 2048)

    const int n4 = (NG * NS) / 4;                      // 2,048,000 threads
    convert_hist_kernel<<<n4 / 256, 256>>>(A, B, seq_idx);
    scan_scatter_kernel<<<1, SCAN_T>>>(genome_idx, seq_idx, pos);
    main_kernel<<<NK, MAIN_THREADS>>>(bias, out);
}